// round 12
// baseline (speedup 1.0000x reference)
#include <cuda_runtime.h>
#include <cstdint>

#define BATCH 8
#define IN_F 4096
#define OUT_F 12288
#define GS 128
#define NG 32
#define OPW 4          // outputs per warp
#define TPB 32         // one warp per CTA; NO intra-CTA sync anywhere
#define NSTG 6         // smem stage slots
#define DEPTH 5        // outstanding cp.async groups

typedef unsigned long long u64;

__device__ float g_sx[BATCH * NG];      // per-batch per-group sums of x

__device__ __forceinline__ u64 pack2(float lo, float hi) {
    u64 r; asm("mov.b64 %0, {%1, %2};" : "=l"(r) : "f"(lo), "f"(hi)); return r;
}
__device__ __forceinline__ void unpack2(u64 v, float& lo, float& hi) {
    asm("mov.b64 {%0, %1}, %2;" : "=f"(lo), "=f"(hi) : "l"(v));
}
__device__ __forceinline__ u64 fma2(u64 a, u64 b, u64 c) {
    u64 d; asm("fma.rn.f32x2 %0, %1, %2, %3;" : "=l"(d) : "l"(a), "l"(b), "l"(c)); return d;
}
__device__ __forceinline__ u64 mul2(u64 a, u64 b) {
    u64 d; asm("mul.rn.f32x2 %0, %1, %2;" : "=l"(d) : "l"(a), "l"(b)); return d;
}
// x: pairs along k, keep resident in L1
__device__ __forceinline__ ulonglong2 ldg_x2(const float* p) {
    ulonglong2 v;
    asm("ld.global.nc.L1::evict_last.v2.u64 {%0,%1}, [%2];"
        : "=l"(v.x), "=l"(v.y) : "l"(p));
    return v;
}
// scales: streaming
__device__ __forceinline__ float4 ldg_cs4(const float* p) {
    float4 v;
    asm("ld.global.cs.v4.f32 {%0,%1,%2,%3}, [%4];"
        : "=f"(v.x), "=f"(v.y), "=f"(v.z), "=f"(v.w) : "l"(p));
    return v;
}
// weights: 16-B async copy, L1-bypass (cg)
__device__ __forceinline__ void cp16(uint32_t dst, const void* src) {
    asm volatile("cp.async.cg.shared.global [%0], [%1], 16;" :: "r"(dst), "l"(src));
}

// ---- prekernel: Sx[b][g] = sum of x over group g (warp per (b,g)) ----
__global__ void prep_kernel(const float* __restrict__ x) {
    const int gt   = blockIdx.x * blockDim.x + threadIdx.x;
    const int w    = gt >> 5;            // 0..255 = b*32 + g
    const int lane = gt & 31;
    const int base = (w >> 5) * IN_F + (w & 31) * GS + lane * 4;
    float4 v = __ldg((const float4*)(x + base));
    float s = (v.x + v.y) + (v.z + v.w);
    #pragma unroll
    for (int off = 16; off > 0; off >>= 1)
        s += __shfl_xor_sync(0xffffffffu, s, off);
    if (lane == 0) g_sx[w] = s;
}

// ---- main kernel: one warp per 4 outputs; per-warp async weight pipeline ----
__global__ void __launch_bounds__(TPB, 13)
w4a32_main(const float* __restrict__ x, const int* __restrict__ qw,
           const float* __restrict__ sc, const float* __restrict__ zr,
           float* __restrict__ out)
{
    __shared__ __align__(16) int ws[NSTG * OPW * GS];   // 6 stages x 2 KB = 12 KB
    __shared__ float bounce[OPW * BATCH];

    const int lane = threadIdx.x;
    const int n0   = blockIdx.x * OPW;
    const int klo  = lane * 4;

    const int* qsrc = qw + (long)n0 * IN_F + klo;
    const uint32_t ws_base = (uint32_t)__cvta_generic_to_shared(ws) + klo * 4;

    // issue one group's weights (this lane's 16 B of each of 4 rows) into slot st
    auto issue = [&](int g, int st) {
        const int* s = qsrc + g * GS;
        const uint32_t dst = ws_base + st * (OPW * GS * 4);
        #pragma unroll
        for (int o = 0; o < OPW; ++o)
            cp16(dst + o * (GS * 4), s + o * IN_F);
    };

    // prologue: fill DEPTH groups
    #pragma unroll
    for (int s = 0; s < DEPTH; ++s) {
        issue(s, s);
        asm volatile("cp.async.commit_group;");
    }

    // scales: register depth 2 (unchanged from R6)
    float4 svbuf[2];
    svbuf[0] = ldg_cs4(sc + n0);
    svbuf[1] = ldg_cs4(sc + OUT_F + n0);

    // x: register depth 1 (pairs along k), L1-resident
    ulonglong2 xcur[BATCH];
    #pragma unroll
    for (int b = 0; b < BATCH; ++b)
        xcur[b] = ldg_x2(x + b * IN_F + klo);

    u64 acc[OPW][BATCH];
    #pragma unroll
    for (int o = 0; o < OPW; ++o)
        #pragma unroll
        for (int b = 0; b < BATCH; ++b) acc[o][b] = 0ull;

    int st = 0, stw = DEPTH;   // read slot, write slot
    #pragma unroll 2
    for (int g = 0; g < NG; ++g) {
        const int cur = g & 1;

        // oldest group (g) complete when <= DEPTH-1 groups remain pending.
        asm volatile("cp.async.wait_group %0;" :: "n"(DEPTH - 1));

        // read this lane's codes from the smem stage (each lane reads only
        // bytes its own cp.async wrote -> per-thread ordering suffices)
        int4 q[OPW];
        {
            const int* wsp = ws + st * (OPW * GS) + klo;
            #pragma unroll
            for (int o = 0; o < OPW; ++o)
                q[o] = *(const int4*)(wsp + o * GS);
        }

        // convert: qs[o] = (s*q0,s*q1),(s*q2,s*q3)
        u64 qs[OPW][2];
        {
            const float4 sv = svbuf[cur];
            const float sa[OPW] = {sv.x, sv.y, sv.z, sv.w};
            #pragma unroll
            for (int o = 0; o < OPW; ++o) {
                u64 s2 = pack2(sa[o], sa[o]);
                qs[o][0] = mul2(pack2((float)q[o].x, (float)q[o].y), s2);
                qs[o][1] = mul2(pack2((float)q[o].z, (float)q[o].w), s2);
            }
        }

        // issue group g+DEPTH (slot just freed is st-1; stw stays DEPTH ahead);
        // ALWAYS commit (possibly-empty group) so wait_group drains the tail.
        if (g + DEPTH < NG) issue(g + DEPTH, stw);
        asm volatile("cp.async.commit_group;");

        // prefetch scales for g+2
        {
            const int gn2 = (g + 2) & (NG - 1);
            svbuf[cur] = ldg_cs4(sc + gn2 * OUT_F + n0);
        }

        // math for group g; per-batch, prefetch x for g+1 right after consuming
        const float* xg1 = x + ((g + 1) & (NG - 1)) * GS + klo;
        #pragma unroll
        for (int b = 0; b < BATCH; ++b) {
            const ulonglong2 xv = xcur[b];
            xcur[b] = ldg_x2(xg1 + b * IN_F);
            #pragma unroll
            for (int o = 0; o < OPW; ++o) {
                acc[o][b] = fma2(xv.x, qs[o][0], acc[o][b]);
                acc[o][b] = fma2(xv.y, qs[o][1], acc[o][b]);
            }
        }

        if (++st == NSTG) st = 0;
        if (++stw == NSTG) stw = 0;
    }

    // ---- pair-halves add, butterfly across 32 lanes ----
    float r[OPW][BATCH];
    #pragma unroll
    for (int o = 0; o < OPW; ++o)
        #pragma unroll
        for (int b = 0; b < BATCH; ++b) {
            float lo, hi; unpack2(acc[o][b], lo, hi);
            r[o][b] = lo + hi;
        }
    #pragma unroll
    for (int off = 16; off > 0; off >>= 1)
        #pragma unroll
        for (int o = 0; o < OPW; ++o)
            #pragma unroll
            for (int b = 0; b < BATCH; ++b)
                r[o][b] += __shfl_xor_sync(0xffffffffu, r[o][b], off);

    if (lane == 0) {
        #pragma unroll
        for (int o = 0; o < OPW; ++o)
            #pragma unroll
            for (int b = 0; b < BATCH; ++b)
                bounce[o * BATCH + b] = r[o][b];
    }
    __syncwarp();

    // 32 results, one per lane; fold in zero/offset term
    const int o = lane >> 3, b = lane & 7;
    const int n = n0 + o;
    float offt = 0.f;
    #pragma unroll
    for (int g2 = 0; g2 < NG; ++g2) {
        float s = __ldg(sc + g2 * OUT_F + n);
        float z = __ldg(zr + g2 * OUT_F + n);
        offt = fmaf(z - 8.f * s, g_sx[b * NG + g2], offt);
    }
    out[b * OUT_F + n] = bounce[lane] + offt;
}

extern "C" void kernel_launch(void* const* d_in, const int* in_sizes, int n_in,
                              void* d_out, int out_size) {
    const float* x  = (const float*)d_in[0];
    const int*   qw = (const int*)d_in[1];
    const float* sc = (const float*)d_in[2];
    const float* zr = (const float*)d_in[3];
    float* out = (float*)d_out;

    prep_kernel<<<32, 256>>>(x);
    w4a32_main<<<OUT_F / OPW, TPB>>>(x, qw, sc, zr, out);   // 3072 x 32
}

// round 13
// speedup vs baseline: 2.0750x; 2.0750x over previous
#include <cuda_runtime.h>
#include <cuda_fp16.h>
#include <cstdint>

#define BATCH 8
#define IN_F 4096
#define OUT_F 12288
#define GS 128
#define NG 32
#define OPW 4          // outputs per warp
#define TPB 32         // one warp per CTA; NO intra-CTA sync anywhere

typedef unsigned long long u64;

__device__ float  g_sx[BATCH * NG];      // per-batch per-group sums of x (fp32, exact)
__device__ __half g_xh[BATCH * IN_F];    // x as fp16 (64 KB, L1-resident)

__device__ __forceinline__ u64 pack2(float lo, float hi) {
    u64 r; asm("mov.b64 %0, {%1, %2};" : "=l"(r) : "f"(lo), "f"(hi)); return r;
}
__device__ __forceinline__ void unpack2(u64 v, float& lo, float& hi) {
    asm("mov.b64 {%0, %1}, %2;" : "=f"(lo), "=f"(hi) : "l"(v));
}
__device__ __forceinline__ u64 fma2(u64 a, u64 b, u64 c) {
    u64 d; asm("fma.rn.f32x2 %0, %1, %2, %3;" : "=l"(d) : "l"(a), "l"(b), "l"(c)); return d;
}
__device__ __forceinline__ u64 mul2(u64 a, u64 b) {
    u64 d; asm("mul.rn.f32x2 %0, %1, %2;" : "=l"(d) : "l"(a), "l"(b)); return d;
}
// weights: streaming, evict-first (protect x in L1)
__device__ __forceinline__ int4 ldg_cs(const int* p) {
    int4 v;
    asm("ld.global.cs.v4.u32 {%0,%1,%2,%3}, [%4];"
        : "=r"(v.x), "=r"(v.y), "=r"(v.z), "=r"(v.w) : "l"(p));
    return v;
}
// x (fp16): 8B per lane, keep resident in L1
__device__ __forceinline__ uint2 ldg_xh(const __half* p) {
    uint2 v;
    asm("ld.global.nc.L1::evict_last.v2.u32 {%0,%1}, [%2];"
        : "=r"(v.x), "=r"(v.y) : "l"(p));
    return v;
}
// scales: streaming
__device__ __forceinline__ float4 ldg_cs4(const float* p) {
    float4 v;
    asm("ld.global.cs.v4.f32 {%0,%1,%2,%3}, [%4];"
        : "=f"(v.x), "=f"(v.y), "=f"(v.z), "=f"(v.w) : "l"(p));
    return v;
}

// ---- prekernel: x -> fp16, plus Sx[b][g] group sums (warp per (b,g)) ----
__global__ void prep_kernel(const float* __restrict__ x) {
    const int gt   = blockIdx.x * blockDim.x + threadIdx.x;
    const int w    = gt >> 5;            // 0..255 = b*32 + g
    const int lane = gt & 31;
    const int base = (w >> 5) * IN_F + (w & 31) * GS + lane * 4;

    float4 v = __ldg((const float4*)(x + base));

    __half2 h01 = __floats2half2_rn(v.x, v.y);
    __half2 h23 = __floats2half2_rn(v.z, v.w);
    uint2 p;
    p.x = *(const unsigned*)&h01;
    p.y = *(const unsigned*)&h23;
    *(uint2*)(g_xh + base) = p;

    float s = (v.x + v.y) + (v.z + v.w);
    #pragma unroll
    for (int off = 16; off > 0; off >>= 1)
        s += __shfl_xor_sync(0xffffffffu, s, off);
    if (lane == 0) g_sx[w] = s;
}

// ---- main kernel: one warp per 4 outputs; FRONT-BATCHED loads ----
__global__ void __launch_bounds__(TPB, 12)
w4a32_main(const int* __restrict__ qw,
           const float* __restrict__ sc, const float* __restrict__ zr,
           float* __restrict__ out)
{
    __shared__ float bounce[OPW * BATCH];

    const int lane = threadIdx.x;
    const int n0   = blockIdx.x * OPW;
    const int klo  = lane * 4;

    const int* qbase = qw + (long)n0 * IN_F + klo;

    // weights: register pipeline depth 2 (parity buffers)
    int4 qbuf[2][OPW];
    #pragma unroll
    for (int s = 0; s < 2; ++s)
        #pragma unroll
        for (int o = 0; o < OPW; ++o)
            qbuf[s][o] = ldg_cs(qbase + s * GS + o * IN_F);

    // scales: single buffer, distance 1 (copied to local before overwrite)
    float4 sv0 = ldg_cs4(sc + n0);

    // x (fp16 pairs): double buffer, distance 1
    uint2 xb[2][BATCH];
    #pragma unroll
    for (int b = 0; b < BATCH; ++b)
        xb[0][b] = ldg_xh(g_xh + b * IN_F + klo);

    u64 acc[OPW][BATCH];
    #pragma unroll
    for (int o = 0; o < OPW; ++o)
        #pragma unroll
        for (int b = 0; b < BATCH; ++b) acc[o][b] = 0ull;

    #pragma unroll 2
    for (int g = 0; g < NG; ++g) {
        const int cur = g & 1;

        // capture current group's operands before their buffers are refilled
        int4 q[OPW];
        #pragma unroll
        for (int o = 0; o < OPW; ++o) q[o] = qbuf[cur][o];
        const float4 sv = sv0;

        // ================= FRONT-BATCHED LOAD BLOCK (13 LDGs, no consumers) ==
        // x for group g+1
        {
            const __half* xg1 = g_xh + ((g + 1) & (NG - 1)) * GS + klo;
            #pragma unroll
            for (int b = 0; b < BATCH; ++b)
                xb[cur ^ 1][b] = ldg_xh(xg1 + b * IN_F);
        }
        // weights for group g+2
        {
            const int gn2 = (g + 2) & (NG - 1);
            #pragma unroll
            for (int o = 0; o < OPW; ++o)
                qbuf[cur][o] = ldg_cs(qbase + gn2 * GS + o * IN_F);
        }
        // scales for group g+1
        sv0 = ldg_cs4(sc + ((g + 1) & (NG - 1)) * OUT_F + n0);
        // =====================================================================

        // convert current weight group: qs[o] = (s*q0,s*q1),(s*q2,s*q3)
        u64 qs[OPW][2];
        {
            const float sa[OPW] = {sv.x, sv.y, sv.z, sv.w};
            #pragma unroll
            for (int o = 0; o < OPW; ++o) {
                u64 s2 = pack2(sa[o], sa[o]);
                qs[o][0] = mul2(pack2((float)q[o].x, (float)q[o].y), s2);
                qs[o][1] = mul2(pack2((float)q[o].z, (float)q[o].w), s2);
            }
        }

        // math for group g from xb[cur] (loaded at top of iteration g-1)
        #pragma unroll
        for (int b = 0; b < BATCH; ++b) {
            const uint2 xv = xb[cur][b];
            float2 f01 = __half22float2(*(const __half2*)&xv.x);
            float2 f23 = __half22float2(*(const __half2*)&xv.y);
            u64 x01 = pack2(f01.x, f01.y);
            u64 x23 = pack2(f23.x, f23.y);
            #pragma unroll
            for (int o = 0; o < OPW; ++o) {
                acc[o][b] = fma2(x01, qs[o][0], acc[o][b]);
                acc[o][b] = fma2(x23, qs[o][1], acc[o][b]);
            }
        }
    }

    // ---- pair-halves add, butterfly across 32 lanes ----
    float r[OPW][BATCH];
    #pragma unroll
    for (int o = 0; o < OPW; ++o)
        #pragma unroll
        for (int b = 0; b < BATCH; ++b) {
            float lo, hi; unpack2(acc[o][b], lo, hi);
            r[o][b] = lo + hi;
        }
    #pragma unroll
    for (int off = 16; off > 0; off >>= 1)
        #pragma unroll
        for (int o = 0; o < OPW; ++o)
            #pragma unroll
            for (int b = 0; b < BATCH; ++b)
                r[o][b] += __shfl_xor_sync(0xffffffffu, r[o][b], off);

    if (lane == 0) {
        #pragma unroll
        for (int o = 0; o < OPW; ++o)
            #pragma unroll
            for (int b = 0; b < BATCH; ++b)
                bounce[o * BATCH + b] = r[o][b];
    }
    __syncwarp();

    // 32 results, one per lane; fold in zero/offset term
    const int o = lane >> 3, b = lane & 7;
    const int n = n0 + o;
    float offt = 0.f;
    #pragma unroll
    for (int g2 = 0; g2 < NG; ++g2) {
        float s = __ldg(sc + g2 * OUT_F + n);
        float z = __ldg(zr + g2 * OUT_F + n);
        offt = fmaf(z - 8.f * s, g_sx[b * NG + g2], offt);
    }
    out[b * OUT_F + n] = bounce[lane] + offt;
}

extern "C" void kernel_launch(void* const* d_in, const int* in_sizes, int n_in,
                              void* d_out, int out_size) {
    const float* x  = (const float*)d_in[0];
    const int*   qw = (const int*)d_in[1];
    const float* sc = (const float*)d_in[2];
    const float* zr = (const float*)d_in[3];
    float* out = (float*)d_out;

    prep_kernel<<<32, 256>>>(x);
    w4a32_main<<<OUT_F / OPW, TPB>>>(qw, sc, zr, out);   // 3072 x 32
}